// round 14
// baseline (speedup 1.0000x reference)
#include <cuda_runtime.h>
#include <cstdint>

#define N_NODES 50000
#define N_EDGES 600000
#define D 128
#define M_PAD 50048        // 782 * 64
#define TILE_M 64
#define N_TILES 782
#define SCAN_B 49          // ceil(50000/1024)

// Scratch (__device__ globals; no runtime allocation).
// g_agg pad rows [50000,50048) never written -> stay BSS-zero (deterministic).
__device__ float g_agg[(size_t)M_PAD * D];
__device__ int g_is64;
__device__ int g_deg[N_NODES];
__device__ int g_psum[N_NODES];
__device__ int g_off[N_NODES];
__device__ int g_cur[N_NODES];
__device__ int g_btot[SCAN_B];
__device__ int g_btot_ex[SCAN_B];
__device__ int g_esrc[N_EDGES];

// ---- edge decode (int32 vs int64 buffers) ----
__device__ __forceinline__ void edge_sd(const int* ei, int e, int& src, int& dst) {
    if (g_is64) {
        src = ei[2 * e];
        dst = ei[2 * (N_EDGES + e)];
    } else {
        src = ei[e];
        dst = ei[N_EDGES + e];
    }
}

__global__ void probe_kernel(const int* __restrict__ ei) {
    __shared__ int nonzero;
    if (threadIdx.x == 0) nonzero = 0;
    __syncthreads();
    for (int i = threadIdx.x; i < 4096; i += blockDim.x)
        if (ei[2 * i + 1] != 0) nonzero = 1;
    __syncthreads();
    if (threadIdx.x == 0) g_is64 = (nonzero == 0) ? 1 : 0;
}

__global__ void zero_deg_kernel() {
    int i = blockIdx.x * blockDim.x + threadIdx.x;
    if (i < N_NODES) g_deg[i] = 0;
}

__global__ void hist_kernel(const int* __restrict__ ei) {
    int e = blockIdx.x * blockDim.x + threadIdx.x;
    if (e >= N_EDGES) return;
    int src, dst;
    edge_sd(ei, e, src, dst);
    if ((unsigned)src >= (unsigned)N_NODES || (unsigned)dst >= (unsigned)N_NODES)
        return;
    atomicAdd(&g_deg[dst], 1);
}

__global__ void __launch_bounds__(1024) scan_block_kernel() {
    __shared__ int s[1024];
    int t = threadIdx.x;
    int i = blockIdx.x * 1024 + t;
    int v = (i < N_NODES) ? g_deg[i] : 0;
    s[t] = v;
    __syncthreads();
#pragma unroll
    for (int d = 1; d < 1024; d <<= 1) {
        int add = (t >= d) ? s[t - d] : 0;
        __syncthreads();
        s[t] += add;
        __syncthreads();
    }
    if (i < N_NODES) g_psum[i] = s[t] - v;
    if (t == 1023) g_btot[blockIdx.x] = s[t];
}

__global__ void scan_tot_kernel() {
    __shared__ int s[64];
    int t = threadIdx.x;
    int v = (t < SCAN_B) ? g_btot[t] : 0;
    s[t] = v;
    __syncthreads();
#pragma unroll
    for (int d = 1; d < 64; d <<= 1) {
        int add = (t >= d) ? s[t - d] : 0;
        __syncthreads();
        s[t] += add;
        __syncthreads();
    }
    if (t < SCAN_B) g_btot_ex[t] = s[t] - v;
}

__global__ void finalize_off_kernel() {
    int i = blockIdx.x * blockDim.x + threadIdx.x;
    if (i < N_NODES) {
        int o = g_psum[i] + g_btot_ex[i >> 10];
        g_off[i] = o;
        g_cur[i] = o;
    }
}

__global__ void fill_kernel(const int* __restrict__ ei) {
    int e = blockIdx.x * blockDim.x + threadIdx.x;
    if (e >= N_EDGES) return;
    int src, dst;
    edge_sd(ei, e, src, dst);
    if ((unsigned)src >= (unsigned)N_NODES || (unsigned)dst >= (unsigned)N_NODES)
        return;
    int pos = atomicAdd(&g_cur[dst], 1);
    g_esrc[pos] = src;
}

// Warp per node: agg[n] = (1+eps)x[n] + sum x[src].
__global__ void gather_kernel(const float4* __restrict__ x,
                              const float* __restrict__ eps) {
    int gid = blockIdx.x * blockDim.x + threadIdx.x;
    int n = gid >> 5;
    int lane = gid & 31;
    if (n >= N_NODES) return;
    float s = 1.0f + __ldg(eps);
    int beg = g_off[n];
    int d = g_deg[n];
    float4 a = x[(long long)n * 32 + lane];
    a.x *= s; a.y *= s; a.z *= s; a.w *= s;
    for (int i = 0; i < d; i++) {
        int src = g_esrc[beg + i];
        float4 v = x[(long long)src * 32 + lane];
        a.x += v.x; a.y += v.y; a.z += v.z; a.w += v.w;
    }
    ((float4*)g_agg)[(long long)n * 32 + lane] = a;
}

// ---- tf32 / mma / cp.async helpers ----
__device__ __forceinline__ uint32_t f2tf32(float f) {
    uint32_t r;
    asm("cvt.rna.tf32.f32 %0, %1;" : "=r"(r) : "f"(f));
    return r;
}
__device__ __forceinline__ void split_tf32(float f, uint32_t& hi, uint32_t& lo) {
    hi = f2tf32(f);
    lo = f2tf32(f - __uint_as_float(hi));
}

#define MMA_TF32(c, a, b)                                            \
    asm("mma.sync.aligned.m16n8k8.row.col.f32.tf32.tf32.f32 "        \
        "{%0,%1,%2,%3}, {%4,%5,%6,%7}, {%8,%9}, {%0,%1,%2,%3};"      \
        : "+f"((c)[0]), "+f"((c)[1]), "+f"((c)[2]), "+f"((c)[3])     \
        : "r"((a)[0]), "r"((a)[1]), "r"((a)[2]), "r"((a)[3]),        \
          "r"((b)[0]), "r"((b)[1]))

#define CP_ASYNC16(dst, src)                                         \
    asm volatile("cp.async.cg.shared.global [%0], [%1], 16;" ::      \
        "r"((uint32_t)__cvta_generic_to_shared(dst)), "l"(src))
#define CP_COMMIT()  asm volatile("cp.async.commit_group;" ::: "memory")
#define CP_WAIT(n)   asm volatile("cp.async.wait_group %0;" :: "n"(n) : "memory")

// Dynamic smem layout (float offsets):
//   hs : [64][132]   h tile    0      (33792 B)
//   As : [2][64][20] agg tiles 8448   (10240 B)
//   Bs : [2][16][136] W tiles  11008  (17408 B)
#define HS_OFF 0
#define AS_OFF 8448
#define BS_OFF 11008
#define SMEM_BYTES 61440

// Fused MLP: out = relu(relu(agg@W1+b1)@W2+b2), 64-row tile per CTA.
// 8 warps, 32x32 warp tiles; 3 CTAs/SM (782 CTAs / 444 slots = 2 short waves).
__global__ void __launch_bounds__(256, 3) fused_mlp_kernel(
    const float* __restrict__ A, const float* __restrict__ W1,
    const float* __restrict__ b1, const float* __restrict__ W2,
    const float* __restrict__ b2, float* __restrict__ out) {
    extern __shared__ float sm[];
    float* hs = sm + HS_OFF;     // [row][132]
    float* As = sm + AS_OFF;     // [b][row][20]
    float* Bs = sm + BS_OFF;     // [b][kk][136]

    const int t = threadIdx.x;
    const int lane = t & 31;
    const int wid = t >> 5;
    const int warp_m = wid & 1;   // 2 x 32 rows
    const int warp_n = wid >> 1;  // 4 x 32 cols
    const int m0 = blockIdx.x * TILE_M;
    const int q = lane >> 2;
    const int r4 = lane & 3;

    float acc[2][4][4];
#pragma unroll
    for (int i = 0; i < 2; i++)
#pragma unroll
        for (int j = 0; j < 4; j++)
#pragma unroll
            for (int c = 0; c < 4; c++) acc[i][j][c] = 0.0f;

    // ---- phase-1 tile loader: agg (64x16) + W1 (16x128), BK=16 ----
    auto load_tile1 = [&](int kc, int b) {
        {   // A: 256 float4, 1 per thread
            int row = t >> 2;
            int k4 = (t & 3) * 4;
            CP_ASYNC16(&As[(b * 64 + row) * 20 + k4],
                       A + (long long)(m0 + row) * D + kc * 16 + k4);
        }
#pragma unroll
        for (int l = 0; l < 2; l++) {   // B: 512 float4, 2 per thread
            int j = t + l * 256;
            int kk = j >> 5;
            int c4 = (j & 31) * 4;
            CP_ASYNC16(&Bs[(b * 16 + kk) * 136 + c4],
                       W1 + (long long)(kc * 16 + kk) * D + c4);
        }
    };

    load_tile1(0, 0);
    CP_COMMIT();

    for (int kc = 0; kc < 8; kc++) {
        int b = kc & 1;
        if (kc < 7) {
            load_tile1(kc + 1, b ^ 1);
            CP_COMMIT();
            CP_WAIT(1);
        } else {
            CP_WAIT(0);
        }
        __syncthreads();

#pragma unroll
        for (int kk8 = 0; kk8 < 16; kk8 += 8) {
            int kr = kk8 + r4;
            uint32_t ah[2][4], al[2][4];
#pragma unroll
            for (int i = 0; i < 2; i++) {
                int rm = warp_m * 32 + i * 16 + q;
                split_tf32(As[(b * 64 + rm) * 20 + kr],         ah[i][0], al[i][0]);
                split_tf32(As[(b * 64 + rm + 8) * 20 + kr],     ah[i][1], al[i][1]);
                split_tf32(As[(b * 64 + rm) * 20 + kr + 4],     ah[i][2], al[i][2]);
                split_tf32(As[(b * 64 + rm + 8) * 20 + kr + 4], ah[i][3], al[i][3]);
            }
            uint32_t bh[4][2], bl[4][2];
#pragma unroll
            for (int j = 0; j < 4; j++) {
                int cn = warp_n * 32 + j * 8 + q;
                split_tf32(Bs[(b * 16 + kr) * 136 + cn],     bh[j][0], bl[j][0]);
                split_tf32(Bs[(b * 16 + kr + 4) * 136 + cn], bh[j][1], bl[j][1]);
            }
#pragma unroll
            for (int i = 0; i < 2; i++)
#pragma unroll
                for (int j = 0; j < 4; j++) {
                    MMA_TF32(acc[i][j], ah[i], bh[j]);
                    MMA_TF32(acc[i][j], ah[i], bl[j]);
                    MMA_TF32(acc[i][j], al[i], bh[j]);
                }
        }
        __syncthreads();
    }

    // ---- phase-1 epilogue: h tile -> smem (local rows) ----
#pragma unroll
    for (int j = 0; j < 4; j++) {
        int col = warp_n * 32 + j * 8 + 2 * r4;
        float bx = __ldg(b1 + col);
        float by = __ldg(b1 + col + 1);
#pragma unroll
        for (int i = 0; i < 2; i++) {
            int row0 = warp_m * 32 + i * 16 + q;
            int row1 = row0 + 8;
            *(float2*)(hs + row0 * 132 + col) =
                make_float2(fmaxf(acc[i][j][0] + bx, 0.0f),
                            fmaxf(acc[i][j][1] + by, 0.0f));
            *(float2*)(hs + row1 * 132 + col) =
                make_float2(fmaxf(acc[i][j][2] + bx, 0.0f),
                            fmaxf(acc[i][j][3] + by, 0.0f));
        }
    }
    __syncthreads();

    // ---- phase 2: acc = h @ W2 ----
#pragma unroll
    for (int i = 0; i < 2; i++)
#pragma unroll
        for (int j = 0; j < 4; j++)
#pragma unroll
            for (int c = 0; c < 4; c++) acc[i][j][c] = 0.0f;

    auto load_tile2 = [&](int kc, int b) {
#pragma unroll
        for (int l = 0; l < 2; l++) {
            int j = t + l * 256;
            int kk = j >> 5;
            int c4 = (j & 31) * 4;
            CP_ASYNC16(&Bs[(b * 16 + kk) * 136 + c4],
                       W2 + (long long)(kc * 16 + kk) * D + c4);
        }
    };

    load_tile2(0, 0);
    CP_COMMIT();

    for (int kc = 0; kc < 8; kc++) {
        int b = kc & 1;
        if (kc < 7) {
            load_tile2(kc + 1, b ^ 1);
            CP_COMMIT();
            CP_WAIT(1);
        } else {
            CP_WAIT(0);
        }
        __syncthreads();

#pragma unroll
        for (int kk8 = 0; kk8 < 16; kk8 += 8) {
            int kr = kc * 16 + kk8 + r4;   // absolute h column
            uint32_t ah[2][4], al[2][4];
#pragma unroll
            for (int i = 0; i < 2; i++) {
                int rm = warp_m * 32 + i * 16 + q;
                split_tf32(hs[rm * 132 + kr],           ah[i][0], al[i][0]);
                split_tf32(hs[(rm + 8) * 132 + kr],     ah[i][1], al[i][1]);
                split_tf32(hs[rm * 132 + kr + 4],       ah[i][2], al[i][2]);
                split_tf32(hs[(rm + 8) * 132 + kr + 4], ah[i][3], al[i][3]);
            }
            int kl = kk8 + r4;
            uint32_t bh[4][2], bl[4][2];
#pragma unroll
            for (int j = 0; j < 4; j++) {
                int cn = warp_n * 32 + j * 8 + q;
                split_tf32(Bs[(b * 16 + kl) * 136 + cn],     bh[j][0], bl[j][0]);
                split_tf32(Bs[(b * 16 + kl + 4) * 136 + cn], bh[j][1], bl[j][1]);
            }
#pragma unroll
            for (int i = 0; i < 2; i++)
#pragma unroll
                for (int j = 0; j < 4; j++) {
                    MMA_TF32(acc[i][j], ah[i], bh[j]);
                    MMA_TF32(acc[i][j], ah[i], bl[j]);
                    MMA_TF32(acc[i][j], al[i], bh[j]);
                }
        }
        __syncthreads();
    }

    // ---- phase-2 epilogue: final out (guarded to N_NODES) ----
#pragma unroll
    for (int j = 0; j < 4; j++) {
        int col = warp_n * 32 + j * 8 + 2 * r4;
        float bx = __ldg(b2 + col);
        float by = __ldg(b2 + col + 1);
#pragma unroll
        for (int i = 0; i < 2; i++) {
            int row0 = m0 + warp_m * 32 + i * 16 + q;
            int row1 = row0 + 8;
            if (row0 < N_NODES)
                *(float2*)(out + (long long)row0 * D + col) =
                    make_float2(fmaxf(acc[i][j][0] + bx, 0.0f),
                                fmaxf(acc[i][j][1] + by, 0.0f));
            if (row1 < N_NODES)
                *(float2*)(out + (long long)row1 * D + col) =
                    make_float2(fmaxf(acc[i][j][2] + bx, 0.0f),
                                fmaxf(acc[i][j][3] + by, 0.0f));
        }
    }
}

extern "C" void kernel_launch(void* const* d_in, const int* in_sizes, int n_in,
                              void* d_out, int out_size) {
    const float* x = (const float*)d_in[0];
    const int* ei = (const int*)d_in[1];
    const float* W1 = (const float*)d_in[2];
    const float* b1 = (const float*)d_in[3];
    const float* W2 = (const float*)d_in[4];
    const float* b2 = (const float*)d_in[5];
    const float* eps = (const float*)d_in[6];
    float* out = (float*)d_out;

    static float* agg = nullptr;
    if (!agg) {
        cudaGetSymbolAddress((void**)&agg, g_agg);
        cudaFuncSetAttribute(fused_mlp_kernel,
                             cudaFuncAttributeMaxDynamicSharedMemorySize,
                             SMEM_BYTES);
    }

    const int EB = (N_EDGES + 255) / 256;

    probe_kernel<<<1, 256>>>(ei);
    zero_deg_kernel<<<(N_NODES + 255) / 256, 256>>>();
    hist_kernel<<<EB, 256>>>(ei);
    scan_block_kernel<<<SCAN_B, 1024>>>();
    scan_tot_kernel<<<1, 64>>>();
    finalize_off_kernel<<<(N_NODES + 255) / 256, 256>>>();
    fill_kernel<<<EB, 256>>>(ei);
    gather_kernel<<<(N_NODES * 32 + 255) / 256, 256>>>((const float4*)x, eps);

    fused_mlp_kernel<<<N_TILES, 256, SMEM_BYTES>>>(agg, W1, b1, W2, b2, out);
}

// round 16
// speedup vs baseline: 1.3382x; 1.3382x over previous
#include <cuda_runtime.h>
#include <cstdint>

#define N_NODES 50000
#define N_EDGES 600000
#define D 128
#define KP 64              // k-pairs per row (D/2)
#define M_PAD 50048        // 391 * 128
#define N_TILES 391
#define SCAN_B 49

// ---- scratch (__device__ globals) ----
// Pre-split bf16 operands: value = hi + lo, each buffer holds packed bf16x2
// k-pairs (elem 2kp in low half, 2kp+1 in high half).
// Pad rows of g_aggp_* never written -> BSS zero -> bf16 0.0 (valid).
__device__ uint32_t g_aggp_hi[(size_t)M_PAD * KP];
__device__ uint32_t g_aggp_lo[(size_t)M_PAD * KP];
__device__ uint32_t g_w1p_hi[KP * D];
__device__ uint32_t g_w1p_lo[KP * D];
__device__ uint32_t g_w2p_hi[KP * D];
__device__ uint32_t g_w2p_lo[KP * D];
__device__ int g_is64;
__device__ int g_deg[N_NODES];
__device__ int g_psum[N_NODES];
__device__ int g_off[N_NODES];
__device__ int g_cur[N_NODES];
__device__ int g_btot[SCAN_B];
__device__ int g_btot_ex[SCAN_B];
__device__ int g_esrc[N_EDGES];

// Split two floats into packed bf16x2 hi and lo pairs (f0 -> low half).
__device__ __forceinline__ void splitpack(float f0, float f1,
                                          uint32_t& hi, uint32_t& lo) {
    asm("cvt.rn.bf16x2.f32 %0, %1, %2;" : "=r"(hi) : "f"(f1), "f"(f0));
    float h0 = __uint_as_float(hi << 16);
    float h1 = __uint_as_float(hi & 0xFFFF0000u);
    asm("cvt.rn.bf16x2.f32 %0, %1, %2;" : "=r"(lo) : "f"(f1 - h1), "f"(f0 - h0));
}

// ---- edge decode ----
__device__ __forceinline__ void edge_sd(const int* ei, int e, int& src, int& dst) {
    if (g_is64) {
        src = ei[2 * e];
        dst = ei[2 * (N_EDGES + e)];
    } else {
        src = ei[e];
        dst = ei[N_EDGES + e];
    }
}

__global__ void probe_kernel(const int* __restrict__ ei) {
    __shared__ int nonzero;
    if (threadIdx.x == 0) nonzero = 0;
    __syncthreads();
    for (int i = threadIdx.x; i < 4096; i += blockDim.x)
        if (ei[2 * i + 1] != 0) nonzero = 1;
    __syncthreads();
    if (threadIdx.x == 0) g_is64 = (nonzero == 0) ? 1 : 0;
}

__global__ void zero_deg_kernel() {
    int i = blockIdx.x * blockDim.x + threadIdx.x;
    if (i < N_NODES) g_deg[i] = 0;
}

__global__ void hist_kernel(const int* __restrict__ ei) {
    int e = blockIdx.x * blockDim.x + threadIdx.x;
    if (e >= N_EDGES) return;
    int src, dst;
    edge_sd(ei, e, src, dst);
    if ((unsigned)src >= (unsigned)N_NODES || (unsigned)dst >= (unsigned)N_NODES)
        return;
    atomicAdd(&g_deg[dst], 1);
}

__global__ void __launch_bounds__(1024) scan_block_kernel() {
    __shared__ int s[1024];
    int t = threadIdx.x;
    int i = blockIdx.x * 1024 + t;
    int v = (i < N_NODES) ? g_deg[i] : 0;
    s[t] = v;
    __syncthreads();
#pragma unroll
    for (int d = 1; d < 1024; d <<= 1) {
        int add = (t >= d) ? s[t - d] : 0;
        __syncthreads();
        s[t] += add;
        __syncthreads();
    }
    if (i < N_NODES) g_psum[i] = s[t] - v;
    if (t == 1023) g_btot[blockIdx.x] = s[t];
}

__global__ void scan_tot_kernel() {
    __shared__ int s[64];
    int t = threadIdx.x;
    int v = (t < SCAN_B) ? g_btot[t] : 0;
    s[t] = v;
    __syncthreads();
#pragma unroll
    for (int d = 1; d < 64; d <<= 1) {
        int add = (t >= d) ? s[t - d] : 0;
        __syncthreads();
        s[t] += add;
        __syncthreads();
    }
    if (t < SCAN_B) g_btot_ex[t] = s[t] - v;
}

__global__ void finalize_off_kernel() {
    int i = blockIdx.x * blockDim.x + threadIdx.x;
    if (i < N_NODES) {
        int o = g_psum[i] + g_btot_ex[i >> 10];
        g_off[i] = o;
        g_cur[i] = o;
    }
}

__global__ void fill_kernel(const int* __restrict__ ei) {
    int e = blockIdx.x * blockDim.x + threadIdx.x;
    if (e >= N_EDGES) return;
    int src, dst;
    edge_sd(ei, e, src, dst);
    if ((unsigned)src >= (unsigned)N_NODES || (unsigned)dst >= (unsigned)N_NODES)
        return;
    int pos = atomicAdd(&g_cur[dst], 1);
    g_esrc[pos] = src;
}

// Pre-split W1/W2 into packed bf16x2 k-pair layout: Wp[kp][n].
__global__ void split_w_kernel(const float* __restrict__ W1,
                               const float* __restrict__ W2) {
    int i = blockIdx.x * blockDim.x + threadIdx.x;
    if (i >= KP * D) return;
    int kp = i >> 7;
    int n = i & 127;
    uint32_t hi, lo;
    splitpack(W1[(2 * kp) * D + n], W1[(2 * kp + 1) * D + n], hi, lo);
    g_w1p_hi[i] = hi;
    g_w1p_lo[i] = lo;
    splitpack(W2[(2 * kp) * D + n], W2[(2 * kp + 1) * D + n], hi, lo);
    g_w2p_hi[i] = hi;
    g_w2p_lo[i] = lo;
}

// Warp per node: agg[n] = (1+eps)x[n] + sum x[src]; writes split bf16 pairs.
__global__ void gather_kernel(const float4* __restrict__ x,
                              const float* __restrict__ eps) {
    int gid = blockIdx.x * blockDim.x + threadIdx.x;
    int n = gid >> 5;
    int lane = gid & 31;
    if (n >= N_NODES) return;
    float s = 1.0f + __ldg(eps);
    int beg = g_off[n];
    int d = g_deg[n];
    float4 a = x[(long long)n * 32 + lane];
    a.x *= s; a.y *= s; a.z *= s; a.w *= s;
    for (int i = 0; i < d; i++) {
        int src = g_esrc[beg + i];
        float4 v = x[(long long)src * 32 + lane];
        a.x += v.x; a.y += v.y; a.z += v.z; a.w += v.w;
    }
    uint32_t h0, l0, h1, l1;
    splitpack(a.x, a.y, h0, l0);
    splitpack(a.z, a.w, h1, l1);
    long long base = (long long)n * KP + lane * 2;
    *(uint2*)&g_aggp_hi[base] = make_uint2(h0, h1);
    *(uint2*)&g_aggp_lo[base] = make_uint2(l0, l1);
}

#define MMA_BF16(c, a, b)                                            \
    asm("mma.sync.aligned.m16n8k16.row.col.f32.bf16.bf16.f32 "       \
        "{%0,%1,%2,%3}, {%4,%5,%6,%7}, {%8,%9}, {%0,%1,%2,%3};"      \
        : "+f"((c)[0]), "+f"((c)[1]), "+f"((c)[2]), "+f"((c)[3])     \
        : "r"((a)[0]), "r"((a)[1]), "r"((a)[2]), "r"((a)[3]),        \
          "r"((b)[0]), "r"((b)[1]))

#define CP_ASYNC16(dst, src)                                         \
    asm volatile("cp.async.cg.shared.global [%0], [%1], 16;" ::      \
        "r"((uint32_t)__cvta_generic_to_shared(dst)), "l"(src))
#define CP_COMMIT()  asm volatile("cp.async.commit_group;" ::: "memory")
#define CP_WAIT(n)   asm volatile("cp.async.wait_group %0;" :: "n"(n) : "memory")

// Dynamic smem layout (uint32 offsets). hs row stride 68 = 64 k-pairs + 4 pad
// (phase-2 A-frag banks (68q + r4) mod 32 = (4q + r4): conflict-free).
//   hs_hi [128][68]  0       (8704)
//   hs_lo [128][68]  8704    (8704)
//   As_hi [2][128][12] 17408 (3072)
//   As_lo            20480   (3072)
//   Bs_hi [2][8][132] 23552  (2112)
//   Bs_lo            25664   (2112)   end 27776 u32 = 111104 B
#define HSH 0
#define HSL 8704
#define ASH 17408
#define ASL 20480
#define BSH 23552
#define BSL 25664
#define HS_STRIDE 68
#define SMEM_BYTES 111104

// Fused MLP on pre-split bf16 pairs: out = relu(relu(agg@W1+b1)@W2+b2).
// 128-row tile/CTA, BK=16 (1 k16 MMA step per tile), 8 warps (64x32 tiles),
// cp.async double buffer, 3-term bf16 split (err ~2^-16).
__global__ void __launch_bounds__(256, 2) fused_mlp_kernel(
    const uint32_t* __restrict__ Ahi, const uint32_t* __restrict__ Alo,
    const uint32_t* __restrict__ W1hi, const uint32_t* __restrict__ W1lo,
    const float* __restrict__ b1,
    const uint32_t* __restrict__ W2hi, const uint32_t* __restrict__ W2lo,
    const float* __restrict__ b2, float* __restrict__ out) {
    extern __shared__ uint32_t sm[];
    uint32_t* hs_hi = sm + HSH;   // [row][HS_STRIDE]
    uint32_t* hs_lo = sm + HSL;
    uint32_t* As_hi = sm + ASH;   // [b][row][12]
    uint32_t* As_lo = sm + ASL;
    uint32_t* Bs_hi = sm + BSH;   // [b][kp][132]
    uint32_t* Bs_lo = sm + BSL;

    const int t = threadIdx.x;
    const int lane = t & 31;
    const int wid = t >> 5;
    const int warp_m = wid & 1;
    const int warp_n = wid >> 1;
    const int m0 = blockIdx.x * 128;
    const int q = lane >> 2;
    const int r4 = lane & 3;

    float acc[4][4][4];
#pragma unroll
    for (int i = 0; i < 4; i++)
#pragma unroll
        for (int j = 0; j < 4; j++)
#pragma unroll
            for (int c = 0; c < 4; c++) acc[i][j][c] = 0.0f;

    // phase-1 loader: A (128x8 kp) + W1 (8kp x 128), hi+lo. 4 cp/thread.
    auto load1 = [&](int kc, int b) {
        {
            int row = t >> 1;
            int kp4 = (t & 1) * 4;
            int gsrc = (m0 + row) * KP + kc * 8 + kp4;
            CP_ASYNC16(&As_hi[(b * 128 + row) * 12 + kp4], Ahi + gsrc);
            CP_ASYNC16(&As_lo[(b * 128 + row) * 12 + kp4], Alo + gsrc);
        }
        {
            int kp = t >> 5;
            int n4 = (t & 31) * 4;
            int gsrc = (kc * 8 + kp) * D + n4;
            CP_ASYNC16(&Bs_hi[(b * 8 + kp) * 132 + n4], W1hi + gsrc);
            CP_ASYNC16(&Bs_lo[(b * 8 + kp) * 132 + n4], W1lo + gsrc);
        }
    };

    load1(0, 0);
    CP_COMMIT();

    for (int kc = 0; kc < 8; kc++) {
        int b = kc & 1;
        if (kc < 7) {
            load1(kc + 1, b ^ 1);
            CP_COMMIT();
            CP_WAIT(1);
        } else {
            CP_WAIT(0);
        }
        __syncthreads();

        uint32_t ah[4][4], al[4][4];
#pragma unroll
        for (int i = 0; i < 4; i++) {
            int rm = warp_m * 64 + i * 16 + q;
            int b0 = (b * 128 + rm) * 12;
            int b8 = (b * 128 + rm + 8) * 12;
            ah[i][0] = As_hi[b0 + r4];     al[i][0] = As_lo[b0 + r4];
            ah[i][1] = As_hi[b8 + r4];     al[i][1] = As_lo[b8 + r4];
            ah[i][2] = As_hi[b0 + r4 + 4]; al[i][2] = As_lo[b0 + r4 + 4];
            ah[i][3] = As_hi[b8 + r4 + 4]; al[i][3] = As_lo[b8 + r4 + 4];
        }
        uint32_t bh[4][2], bl[4][2];
#pragma unroll
        for (int j = 0; j < 4; j++) {
            int cn = warp_n * 32 + j * 8 + q;
            bh[j][0] = Bs_hi[(b * 8 + r4) * 132 + cn];
            bl[j][0] = Bs_lo[(b * 8 + r4) * 132 + cn];
            bh[j][1] = Bs_hi[(b * 8 + r4 + 4) * 132 + cn];
            bl[j][1] = Bs_lo[(b * 8 + r4 + 4) * 132 + cn];
        }
#pragma unroll
        for (int i = 0; i < 4; i++)
#pragma unroll
            for (int j = 0; j < 4; j++) {
                MMA_BF16(acc[i][j], ah[i], bh[j]);
                MMA_BF16(acc[i][j], ah[i], bl[j]);
                MMA_BF16(acc[i][j], al[i], bh[j]);
            }
        __syncthreads();
    }

    // phase-1 epilogue: bias+relu, split-pack h into smem (local rows).
#pragma unroll
    for (int j = 0; j < 4; j++) {
        int kp = warp_n * 16 + j * 4 + r4;   // col pair index 0..63
        int col = kp * 2;
        float bx = __ldg(b1 + col);
        float by = __ldg(b1 + col + 1);
#pragma unroll
        for (int i = 0; i < 4; i++) {
            int row0 = warp_m * 64 + i * 16 + q;
            int row1 = row0 + 8;
            uint32_t hi, lo;
            splitpack(fmaxf(acc[i][j][0] + bx, 0.0f),
                      fmaxf(acc[i][j][1] + by, 0.0f), hi, lo);
            hs_hi[row0 * HS_STRIDE + kp] = hi;
            hs_lo[row0 * HS_STRIDE + kp] = lo;
            splitpack(fmaxf(acc[i][j][2] + bx, 0.0f),
                      fmaxf(acc[i][j][3] + by, 0.0f), hi, lo);
            hs_hi[row1 * HS_STRIDE + kp] = hi;
            hs_lo[row1 * HS_STRIDE + kp] = lo;
        }
    }
    __syncthreads();

    // phase 2: acc = h @ W2
#pragma unroll
    for (int i = 0; i < 4; i++)
#pragma unroll
        for (int j = 0; j < 4; j++)
#pragma unroll
            for (int c = 0; c < 4; c++) acc[i][j][c] = 0.0f;

    auto load2 = [&](int kc, int b) {
        int kp = t >> 5;
        int n4 = (t & 31) * 4;
        int gsrc = (kc * 8 + kp) * D + n4;
        CP_ASYNC16(&Bs_hi[(b * 8 + kp) * 132 + n4], W2hi + gsrc);
        CP_ASYNC16(&Bs_lo[(b * 8 + kp) * 132 + n4], W2lo + gsrc);
    };

    load2(0, 0);
    CP_COMMIT();

    for (int kc = 0; kc < 8; kc++) {
        int b = kc & 1;
        if (kc < 7) {
            load2(kc + 1, b ^ 1);
            CP_COMMIT();
            CP_WAIT(1);
        } else {
            CP_WAIT(0);
        }
        __syncthreads();

        uint32_t ah[4][4], al[4][4];
#pragma unroll
        for (int i = 0; i < 4; i++) {
            int rm = warp_m * 64 + i * 16 + q;
            int kpa = kc * 8 + r4;
            ah[i][0] = hs_hi[rm * HS_STRIDE + kpa];
            al[i][0] = hs_lo[rm * HS_STRIDE + kpa];
            ah[i][1] = hs_hi[(rm + 8) * HS_STRIDE + kpa];
            al[i][1] = hs_lo[(rm + 8) * HS_STRIDE + kpa];
            ah[i][2] = hs_hi[rm * HS_STRIDE + kpa + 4];
            al[i][2] = hs_lo[rm * HS_STRIDE + kpa + 4];
            ah[i][3] = hs_hi[(rm + 8) * HS_STRIDE + kpa + 4];
            al[i][3] = hs_lo[(rm + 8) * HS_STRIDE + kpa + 4];
        }
        uint32_t bh[4][2], bl[4][2];
#pragma unroll
        for (int j = 0; j < 4; j++) {
            int cn = warp_n * 32 + j * 8 + q;
            bh[j][0] = Bs_hi[(b * 8 + r4) * 132 + cn];
            bl[j][0] = Bs_lo[(b * 8 + r4) * 132 + cn];
            bh[j][1] = Bs_hi[(b * 8 + r4 + 4) * 132 + cn];
            bl[j][1] = Bs_lo[(b * 8 + r4 + 4) * 132 + cn];
        }
#pragma unroll
        for (int i = 0; i < 4; i++)
#pragma unroll
            for (int j = 0; j < 4; j++) {
                MMA_BF16(acc[i][j], ah[i], bh[j]);
                MMA_BF16(acc[i][j], ah[i], bl[j]);
                MMA_BF16(acc[i][j], al[i], bh[j]);
            }
        __syncthreads();
    }

    // phase-2 epilogue: final out (guarded to N_NODES)
#pragma unroll
    for (int j = 0; j < 4; j++) {
        int col = warp_n * 32 + j * 8 + 2 * r4;
        float bx = __ldg(b2 + col);
        float by = __ldg(b2 + col + 1);
#pragma unroll
        for (int i = 0; i < 4; i++) {
            int row0 = m0 + warp_m * 64 + i * 16 + q;
            int row1 = row0 + 8;
            if (row0 < N_NODES)
                *(float2*)(out + (long long)row0 * D + col) =
                    make_float2(fmaxf(acc[i][j][0] + bx, 0.0f),
                                fmaxf(acc[i][j][1] + by, 0.0f));
            if (row1 < N_NODES)
                *(float2*)(out + (long long)row1 * D + col) =
                    make_float2(fmaxf(acc[i][j][2] + bx, 0.0f),
                                fmaxf(acc[i][j][3] + by, 0.0f));
        }
    }
}

extern "C" void kernel_launch(void* const* d_in, const int* in_sizes, int n_in,
                              void* d_out, int out_size) {
    const float* x = (const float*)d_in[0];
    const int* ei = (const int*)d_in[1];
    const float* W1 = (const float*)d_in[2];
    const float* b1 = (const float*)d_in[3];
    const float* W2 = (const float*)d_in[4];
    const float* b2 = (const float*)d_in[5];
    const float* eps = (const float*)d_in[6];
    float* out = (float*)d_out;

    static uint32_t *ahi = nullptr, *alo = nullptr;
    static uint32_t *w1h = nullptr, *w1l = nullptr, *w2h = nullptr, *w2l = nullptr;
    if (!ahi) {
        cudaGetSymbolAddress((void**)&ahi, g_aggp_hi);
        cudaGetSymbolAddress((void**)&alo, g_aggp_lo);
        cudaGetSymbolAddress((void**)&w1h, g_w1p_hi);
        cudaGetSymbolAddress((void**)&w1l, g_w1p_lo);
        cudaGetSymbolAddress((void**)&w2h, g_w2p_hi);
        cudaGetSymbolAddress((void**)&w2l, g_w2p_lo);
        cudaFuncSetAttribute(fused_mlp_kernel,
                             cudaFuncAttributeMaxDynamicSharedMemorySize,
                             SMEM_BYTES);
    }

    const int EB = (N_EDGES + 255) / 256;

    probe_kernel<<<1, 256>>>(ei);
    zero_deg_kernel<<<(N_NODES + 255) / 256, 256>>>();
    hist_kernel<<<EB, 256>>>(ei);
    scan_block_kernel<<<SCAN_B, 1024>>>();
    scan_tot_kernel<<<1, 64>>>();
    finalize_off_kernel<<<(N_NODES + 255) / 256, 256>>>();
    fill_kernel<<<EB, 256>>>(ei);
    split_w_kernel<<<(KP * D + 255) / 256, 256>>>(W1, W2);
    gather_kernel<<<(N_NODES * 32 + 255) / 256, 256>>>((const float4*)x, eps);

    fused_mlp_kernel<<<N_TILES, 256, SMEM_BYTES>>>(ahi, alo, w1h, w1l, b1,
                                                   w2h, w2l, b2, out);
}